// round 2
// baseline (speedup 1.0000x reference)
#include <cuda_runtime.h>

// Problem constants
#define BB   8
#define CC   256
#define HH   112
#define WWD  112
#define HWSZ 12544          // 112*112
#define CHW  3211264        // 256*12544
#define PP   196            // patch area
#define AA   3136           // 56*56
#define TGD  56

// ---------------- scratch (static device memory; no allocations) -------------
__device__ __align__(256) float d_q[(size_t)BB * CHW];
__device__ __align__(256) float d_k[(size_t)BB * CHW];
__device__ __align__(256) float d_v[(size_t)BB * CHW];
__device__ __align__(256) float d_h[(size_t)BB * CHW];
__device__ __align__(256) float d_qp[(size_t)BB * CC * AA];
__device__ __align__(256) float d_kp[(size_t)BB * CC * AA];
__device__ __align__(256) float d_vp[(size_t)BB * CC * AA];
__device__ __align__(256) float d_hg[(size_t)BB * CC * AA];
__device__ __align__(256) float d_attg[(size_t)BB * AA * AA];      // 314.7 MB
__device__ __align__(256) float d_attp[(size_t)BB * PP * PP];
__device__ __align__(256) float d_attp_part[(size_t)4 * BB * PP * PP];
__device__ float d_gnpart[BB * 128 * 2];
__device__ float d_sc[BB * CC];
__device__ float d_sh[BB * CC];
__device__ float d_effb[3 * BB * CC];

#define FMA4x4(acc, a, bb4) { \
    acc[0]  += a.x * bb4.x; acc[1]  += a.x * bb4.y; acc[2]  += a.x * bb4.z; acc[3]  += a.x * bb4.w; \
    acc[4]  += a.y * bb4.x; acc[5]  += a.y * bb4.y; acc[6]  += a.y * bb4.z; acc[7]  += a.y * bb4.w; \
    acc[8]  += a.z * bb4.x; acc[9]  += a.z * bb4.y; acc[10] += a.z * bb4.z; acc[11] += a.z * bb4.w; \
    acc[12] += a.w * bb4.x; acc[13] += a.w * bb4.y; acc[14] += a.w * bb4.z; acc[15] += a.w * bb4.w; }

// ---------------- GroupNorm stats (two-pass, deterministic) ------------------
__global__ void k_gn_partial(const float* __restrict__ x) {
    int b = blockIdx.x, blk = blockIdx.y, t = threadIdx.x;
    const int chunk = CHW / 128;   // 25088
    const float* xb = x + (size_t)b * CHW + (size_t)blk * chunk;
    float s = 0.f, s2 = 0.f;
    for (int i = t; i < chunk; i += 256) { float v = xb[i]; s += v; s2 += v * v; }
    __shared__ float ss[256], sq[256];
    ss[t] = s; sq[t] = s2; __syncthreads();
    for (int o = 128; o > 0; o >>= 1) {
        if (t < o) { ss[t] += ss[t + o]; sq[t] += sq[t + o]; }
        __syncthreads();
    }
    if (t == 0) {
        d_gnpart[(b * 128 + blk) * 2]     = ss[0];
        d_gnpart[(b * 128 + blk) * 2 + 1] = sq[0];
    }
}

__global__ void k_gn_finalize(const float* __restrict__ gn_w, const float* __restrict__ gn_b) {
    int b = blockIdx.x, t = threadIdx.x;   // 128 threads
    __shared__ float ss[128], sq[128];
    ss[t] = d_gnpart[(b * 128 + t) * 2];
    sq[t] = d_gnpart[(b * 128 + t) * 2 + 1];
    __syncthreads();
    for (int o = 64; o > 0; o >>= 1) {
        if (t < o) { ss[t] += ss[t + o]; sq[t] += sq[t + o]; }
        __syncthreads();
    }
    __shared__ float mu_s, inv_s;
    if (t == 0) {
        float mu = ss[0] / (float)CHW;
        float var = sq[0] / (float)CHW - mu * mu;
        mu_s = mu; inv_s = rsqrtf(var + 1e-5f);
    }
    __syncthreads();
    float mu = mu_s, inv = inv_s;
    for (int c = t; c < CC; c += 128) {
        float sc = inv * gn_w[c];
        d_sc[b * CC + c] = sc;
        d_sh[b * CC + c] = gn_b[c] - mu * sc;
    }
}

// effective bias: eb[m][b][co] = bias[co] + sum_ci W[co,ci] * shift[b,ci]
__global__ void k_effbias(const float* __restrict__ wq, const float* __restrict__ wk,
                          const float* __restrict__ wv, const float* __restrict__ bq,
                          const float* __restrict__ bk, const float* __restrict__ bv) {
    int b = blockIdx.x, m = blockIdx.y, co = threadIdx.x;  // 256 threads
    const float* w  = (m == 0) ? wq : ((m == 1) ? wk : wv);
    const float* bs = (m == 0) ? bq : ((m == 1) ? bk : bv);
    float acc = bs[co];
    const float* sh = d_sh + b * CC;
    for (int ci = 0; ci < CC; ci++) acc += w[co * CC + ci] * sh[ci];
    d_effb[(m * BB + b) * CC + co] = acc;
}

// ---------------- fused GN + QKV GEMM (3 outputs share the X tile) -----------
// Y[co,hw] = sum_ci W[co,ci] * (x[ci,hw]*sc[b,ci]) + effbias
__global__ void __launch_bounds__(256) k_qkv(const float* __restrict__ x,
        const float* __restrict__ wq, const float* __restrict__ wk,
        const float* __restrict__ wv) {
    int b = blockIdx.z, co0 = blockIdx.y * 64, hw0 = blockIdx.x * 64;
    int t = threadIdx.x, tx = t & 15, ty = t >> 4;
    __shared__ float Aq[8][68], Ak[8][68], Av[8][68], Xs[8][68];
    float accq[16], acck[16], accv[16];
#pragma unroll
    for (int i = 0; i < 16; i++) { accq[i] = 0.f; acck[i] = 0.f; accv[i] = 0.f; }
    const float* xb  = x + (size_t)b * CHW + hw0;
    const float* scb = d_sc + b * CC;
    int xkk = t >> 5, xhw = (t & 31) * 2;
    for (int k0 = 0; k0 < CC; k0 += 8) {
#pragma unroll
        for (int r = 0; r < 2; r++) {
            int l = t + r * 256;
            int co = l >> 3, kk = l & 7;
            int gi = (co0 + co) * CC + k0 + kk;
            Aq[kk][co] = wq[gi];
            Ak[kk][co] = wk[gi];
            Av[kk][co] = wv[gi];
        }
        {
            float s = scb[k0 + xkk];
            const float* xp = xb + (size_t)(k0 + xkk) * HWSZ + xhw;
            Xs[xkk][xhw]     = xp[0] * s;
            Xs[xkk][xhw + 1] = xp[1] * s;
        }
        __syncthreads();
#pragma unroll
        for (int kk = 0; kk < 8; kk++) {
            float4 xv = *(const float4*)&Xs[kk][tx * 4];
            float4 a;
            a = *(const float4*)&Aq[kk][ty * 4]; FMA4x4(accq, a, xv);
            a = *(const float4*)&Ak[kk][ty * 4]; FMA4x4(acck, a, xv);
            a = *(const float4*)&Av[kk][ty * 4]; FMA4x4(accv, a, xv);
        }
        __syncthreads();
    }
#pragma unroll
    for (int i = 0; i < 4; i++) {
        int co = co0 + ty * 4 + i;
        float ebq = d_effb[b * CC + co];
        float ebk = d_effb[(BB + b) * CC + co];
        float ebv = d_effb[(2 * BB + b) * CC + co];
        size_t ob = (size_t)b * CHW + (size_t)co * HWSZ + hw0 + tx * 4;
#pragma unroll
        for (int j = 0; j < 4; j++) {
            d_q[ob + j] = accq[i * 4 + j] + ebq;
            d_k[ob + j] = acck[i * 4 + j] + ebk;
            d_v[ob + j] = accv[i * 4 + j] + ebv;
        }
    }
}

// ---------------- 2x2 average pool of q,k,v ---------------------------------
__global__ void k_pool() {
    int i = blockIdx.x * 256 + threadIdx.x;      // < BB*CC*AA
    int xq = i % TGD; int r = i / TGD;
    int yq = r % TGD; r /= TGD;
    int c = r % CC;  int b = r / CC;
    size_t src = (size_t)b * CHW + (size_t)c * HWSZ + (size_t)(yq * 2) * WWD + xq * 2;
    float2 a0, a1;
    a0 = *(const float2*)&d_q[src]; a1 = *(const float2*)&d_q[src + WWD];
    d_qp[i] = 0.25f * (a0.x + a0.y + a1.x + a1.y);
    a0 = *(const float2*)&d_k[src]; a1 = *(const float2*)&d_k[src + WWD];
    d_kp[i] = 0.25f * (a0.x + a0.y + a1.x + a1.y);
    a0 = *(const float2*)&d_v[src]; a1 = *(const float2*)&d_v[src + WWD];
    d_vp[i] = 0.25f * (a0.x + a0.y + a1.x + a1.y);
}

// ---------------- patch logits: att_part[p,q] = sum_d q[d,p] k[d,q] ----------
// split-K into 4 deterministic partials; M=N=196 handled as 4x4 masked 64-tiles
__global__ void __launch_bounds__(256) k_patch_logits() {
    int bz = blockIdx.z; int b = bz >> 2, ks = bz & 3;
    int p0 = blockIdx.y * 64, q0 = blockIdx.x * 64;
    int t = threadIdx.x, tx = t & 15, ty = t >> 4;
    __shared__ float As[16][68], Bs[16][68];
    float acc[16];
#pragma unroll
    for (int i = 0; i < 16; i++) acc[i] = 0.f;
    const float* qb = d_q + (size_t)b * CHW;
    const float* kb = d_k + (size_t)b * CHW;
    int kk = t >> 4, m4 = (t & 15) * 4;
    int kend = (ks + 1) * 4096;
    for (int k0 = ks * 4096; k0 < kend; k0 += 16) {
        float4 va = make_float4(0.f, 0.f, 0.f, 0.f);
        if (p0 + m4 < PP) va = *(const float4*)&qb[(size_t)(k0 + kk) * PP + p0 + m4];
        *(float4*)&As[kk][m4] = va;
        float4 vb = make_float4(0.f, 0.f, 0.f, 0.f);
        if (q0 + m4 < PP) vb = *(const float4*)&kb[(size_t)(k0 + kk) * PP + q0 + m4];
        *(float4*)&Bs[kk][m4] = vb;
        __syncthreads();
#pragma unroll
        for (int u = 0; u < 16; u++) {
            float4 a4 = *(const float4*)&As[u][ty * 4];
            float4 b4 = *(const float4*)&Bs[u][tx * 4];
            FMA4x4(acc, a4, b4);
        }
        __syncthreads();
    }
#pragma unroll
    for (int i = 0; i < 4; i++) {
        int p = p0 + ty * 4 + i;
        if (p >= PP) continue;
#pragma unroll
        for (int j = 0; j < 4; j++) {
            int q = q0 + tx * 4 + j;
            if (q >= PP) continue;
            d_attp_part[(size_t)((ks * BB + b) * PP + p) * PP + q] = acc[i * 4 + j];
        }
    }
}

// reduce split-K partials, scale by 1/128, softmax over axis q
__global__ void k_patch_softmax() {
    int p = blockIdx.x, b = blockIdx.y, t = threadIdx.x;  // 256 threads
    float val = 0.f, v = -1e30f;
    if (t < PP) {
#pragma unroll
        for (int ks = 0; ks < 4; ks++)
            val += d_attp_part[(size_t)((ks * BB + b) * PP + p) * PP + t];
        val *= 0.0078125f;   // (C*S)^-0.5 = 1/128
        v = val;
    }
    __shared__ float red[256];
    red[t] = v; __syncthreads();
    for (int o = 128; o > 0; o >>= 1) {
        if (t < o) red[t] = fmaxf(red[t], red[t + o]);
        __syncthreads();
    }
    float mx = red[0];
    __syncthreads();
    float e = (t < PP) ? __expf(val - mx) : 0.f;
    red[t] = e; __syncthreads();
    for (int o = 128; o > 0; o >>= 1) {
        if (t < o) red[t] += red[t + o];
        __syncthreads();
    }
    float inv = 1.f / red[0];
    if (t < PP) d_attp[(size_t)(b * PP + p) * PP + t] = e * inv;
}

// ---------------- patch h: h[d,q] = sum_p v[d,p] * att[q,p]  (NT GEMM) -------
__global__ void __launch_bounds__(256) k_patch_h() {
    int b = blockIdx.z, m0 = blockIdx.y * 64, q0 = blockIdx.x * 64;
    int t = threadIdx.x, tx = t & 15, ty = t >> 4;
    __shared__ float As[16][68], Bs[16][68];
    float acc[16];
#pragma unroll
    for (int i = 0; i < 16; i++) acc[i] = 0.f;
    const float* vb = d_v + (size_t)b * CHW;
    const float* ab = d_attp + (size_t)b * PP * PP;
    int m = t >> 2, kb4 = (t & 3) * 4;
    for (int k0 = 0; k0 < PP; k0 += 16) {
        float4 va = make_float4(0.f, 0.f, 0.f, 0.f);
        if (k0 + kb4 < PP) va = *(const float4*)&vb[(size_t)(m0 + m) * PP + k0 + kb4];
        As[kb4][m] = va.x; As[kb4 + 1][m] = va.y; As[kb4 + 2][m] = va.z; As[kb4 + 3][m] = va.w;
        float4 vv = make_float4(0.f, 0.f, 0.f, 0.f);
        if (q0 + m < PP && k0 + kb4 < PP) vv = *(const float4*)&ab[(size_t)(q0 + m) * PP + k0 + kb4];
        Bs[kb4][m] = vv.x; Bs[kb4 + 1][m] = vv.y; Bs[kb4 + 2][m] = vv.z; Bs[kb4 + 3][m] = vv.w;
        __syncthreads();
#pragma unroll
        for (int u = 0; u < 16; u++) {
            float4 a4 = *(const float4*)&As[u][ty * 4];
            float4 b4 = *(const float4*)&Bs[u][tx * 4];
            FMA4x4(acc, a4, b4);
        }
        __syncthreads();
    }
#pragma unroll
    for (int i = 0; i < 4; i++) {
        int mm = m0 + ty * 4 + i;
#pragma unroll
        for (int j = 0; j < 4; j++) {
            int q = q0 + tx * 4 + j;
            if (q < PP) d_h[(size_t)b * CHW + (size_t)mm * PP + q] = 0.75f * acc[i * 4 + j];
        }
    }
}

// ---------------- global logits: att[p,q] = sum_c qp[c,p] kp[c,q] ------------
__global__ void __launch_bounds__(256) k_glob_logits() {
    int b = blockIdx.z, p0 = blockIdx.y * 64, q0 = blockIdx.x * 64;
    int t = threadIdx.x, tx = t & 15, ty = t >> 4;
    __shared__ float As[16][68], Bs[16][68];
    float acc[16];
#pragma unroll
    for (int i = 0; i < 16; i++) acc[i] = 0.f;
    const float* qb = d_qp + (size_t)b * CC * AA;
    const float* kb = d_kp + (size_t)b * CC * AA;
    int kk = t >> 4, m4 = (t & 15) * 4;
    for (int k0 = 0; k0 < CC; k0 += 16) {
        *(float4*)&As[kk][m4] = *(const float4*)&qb[(size_t)(k0 + kk) * AA + p0 + m4];
        *(float4*)&Bs[kk][m4] = *(const float4*)&kb[(size_t)(k0 + kk) * AA + q0 + m4];
        __syncthreads();
#pragma unroll
        for (int u = 0; u < 16; u++) {
            float4 a4 = *(const float4*)&As[u][ty * 4];
            float4 b4 = *(const float4*)&Bs[u][tx * 4];
            FMA4x4(acc, a4, b4);
        }
        __syncthreads();
    }
    size_t base = (size_t)b * AA * AA;
#pragma unroll
    for (int i = 0; i < 4; i++) {
        int p = p0 + ty * 4 + i;
#pragma unroll
        for (int j = 0; j < 4; j++) {
            int q = q0 + tx * 4 + j;
            d_attg[base + (size_t)p * AA + q] = acc[i * 4 + j];
        }
    }
}

// row softmax over 3136 keys (applies C^-0.5 scale on read), row cached in smem
__global__ void k_glob_softmax() {
    int p = blockIdx.x, b = blockIdx.y, t = threadIdx.x;  // 256 threads
    float* row = d_attg + (size_t)(b * AA + p) * AA;
    __shared__ float sr[AA];
    __shared__ float red[256];
    float mx = -1e30f;
    for (int i = t; i < AA; i += 256) {
        float v = row[i] * 0.0625f;   // C^-0.5
        sr[i] = v; mx = fmaxf(mx, v);
    }
    red[t] = mx; __syncthreads();
    for (int o = 128; o > 0; o >>= 1) {
        if (t < o) red[t] = fmaxf(red[t], red[t + o]);
        __syncthreads();
    }
    mx = red[0];
    __syncthreads();
    float s = 0.f;
    for (int i = t; i < AA; i += 256) { float e = __expf(sr[i] - mx); sr[i] = e; s += e; }
    red[t] = s; __syncthreads();
    for (int o = 128; o > 0; o >>= 1) {
        if (t < o) red[t] += red[t + o];
        __syncthreads();
    }
    float inv = 1.f / red[0];
    for (int i = t; i < AA; i += 256) row[i] = sr[i] * inv;
}

// ---------------- global h: hg[c,q] = sum_p vp[c,p] * att[q,p] (NT GEMM) -----
__global__ void __launch_bounds__(256) k_glob_h() {
    int b = blockIdx.z, c0 = blockIdx.y * 64, q0 = blockIdx.x * 64;
    int t = threadIdx.x, tx = t & 15, ty = t >> 4;
    __shared__ float As[16][68], Bs[16][68];
    float acc[16];
#pragma unroll
    for (int i = 0; i < 16; i++) acc[i] = 0.f;
    const float* vb = d_vp + (size_t)b * CC * AA;
    const float* ab = d_attg + (size_t)b * AA * AA;
    int m = t >> 2, kb4 = (t & 3) * 4;
    for (int k0 = 0; k0 < AA; k0 += 16) {
        float4 va = *(const float4*)&vb[(size_t)(c0 + m) * AA + k0 + kb4];
        As[kb4][m] = va.x; As[kb4 + 1][m] = va.y; As[kb4 + 2][m] = va.z; As[kb4 + 3][m] = va.w;
        float4 vv = *(const float4*)&ab[(size_t)(q0 + m) * AA + k0 + kb4];
        Bs[kb4][m] = vv.x; Bs[kb4 + 1][m] = vv.y; Bs[kb4 + 2][m] = vv.z; Bs[kb4 + 3][m] = vv.w;
        __syncthreads();
#pragma unroll
        for (int u = 0; u < 16; u++) {
            float4 a4 = *(const float4*)&As[u][ty * 4];
            float4 b4 = *(const float4*)&Bs[u][tx * 4];
            FMA4x4(acc, a4, b4);
        }
        __syncthreads();
    }
#pragma unroll
    for (int i = 0; i < 4; i++) {
        int c = c0 + ty * 4 + i;
#pragma unroll
        for (int j = 0; j < 4; j++) {
            int q = q0 + tx * 4 + j;
            d_hg[(size_t)b * CC * AA + (size_t)c * AA + q] = acc[i * 4 + j];
        }
    }
}

// ---------------- bilinear 56->112 upsample (half-pixel) + combine -----------
__global__ void k_upsample() {
    int i = blockIdx.x * 256 + threadIdx.x;   // < BB*CHW
    int xo = i % WWD; int r = i / WWD;
    int yo = r % HH;  r /= HH;
    int c = r % CC;   int b = r / CC;
    float sx = xo * 0.5f - 0.25f, sy = yo * 0.5f - 0.25f;
    float fx = floorf(sx), fy = floorf(sy);
    float wx = sx - fx, wy = sy - fy;
    int x0 = max((int)fx, 0), x1 = min((int)fx + 1, TGD - 1);
    int y0 = max((int)fy, 0), y1 = min((int)fy + 1, TGD - 1);
    const float* hb = d_hg + (size_t)(b * CC + c) * AA;
    float v00 = hb[y0 * TGD + x0], v01 = hb[y0 * TGD + x1];
    float v10 = hb[y1 * TGD + x0], v11 = hb[y1 * TGD + x1];
    float v = (1.f - wy) * ((1.f - wx) * v00 + wx * v01)
            +        wy  * ((1.f - wx) * v10 + wx * v11);
    d_h[i] += 0.25f * v;   // d_h already holds 0.75*h_patch
}

// ---------------- proj GEMM + residual: out = x + Wp @ h ---------------------
__global__ void __launch_bounds__(256) k_proj(const float* __restrict__ x,
        const float* __restrict__ wp, float* __restrict__ out) {
    int b = blockIdx.z, co0 = blockIdx.y * 64, hw0 = blockIdx.x * 64;
    int t = threadIdx.x, tx = t & 15, ty = t >> 4;
    __shared__ float As[16][68], Bs[16][68];
    float acc[16];
#pragma unroll
    for (int i = 0; i < 16; i++) acc[i] = 0.f;
    int wm = t >> 2, wk4 = (t & 3) * 4;       // W transposed load
    int kk = t >> 4, m4 = (t & 15) * 4;       // H tile load
    for (int k0 = 0; k0 < CC; k0 += 16) {
        float4 w4 = *(const float4*)&wp[(size_t)(co0 + wm) * CC + k0 + wk4];
        As[wk4][wm] = w4.x; As[wk4 + 1][wm] = w4.y; As[wk4 + 2][wm] = w4.z; As[wk4 + 3][wm] = w4.w;
        *(float4*)&Bs[kk][m4] =
            *(const float4*)&d_h[(size_t)b * CHW + (size_t)(k0 + kk) * HWSZ + hw0 + m4];
        __syncthreads();
#pragma unroll
        for (int u = 0; u < 16; u++) {
            float4 a4 = *(const float4*)&As[u][ty * 4];
            float4 b4 = *(const float4*)&Bs[u][tx * 4];
            FMA4x4(acc, a4, b4);
        }
        __syncthreads();
    }
#pragma unroll
    for (int i = 0; i < 4; i++) {
        int co = co0 + ty * 4 + i;
        size_t ob = (size_t)b * CHW + (size_t)co * HWSZ + hw0 + tx * 4;
#pragma unroll
        for (int j = 0; j < 4; j++)
            out[ob + j] = x[ob + j] + acc[i * 4 + j];
    }
}

// ---------------- launcher ---------------------------------------------------
extern "C" void kernel_launch(void* const* d_in, const int* in_sizes, int n_in,
                              void* d_out, int out_size) {
    const float* x     = (const float*)d_in[0];
    const float* gn_w  = (const float*)d_in[1];
    const float* gn_b  = (const float*)d_in[2];
    const float* wq    = (const float*)d_in[3];
    const float* bq    = (const float*)d_in[4];
    const float* wk    = (const float*)d_in[5];
    const float* bk    = (const float*)d_in[6];
    const float* wv    = (const float*)d_in[7];
    const float* bv    = (const float*)d_in[8];
    const float* wproj = (const float*)d_in[9];
    float* out = (float*)d_out;

    k_gn_partial<<<dim3(BB, 128), 256>>>(x);
    k_gn_finalize<<<BB, 128>>>(gn_w, gn_b);
    k_effbias<<<dim3(BB, 3), 256>>>(wq, wk, wv, bq, bk, bv);
    k_qkv<<<dim3(196, 4, BB), 256>>>(x, wq, wk, wv);
    k_pool<<<(BB * CC * AA) / 256, 256>>>();
    k_patch_logits<<<dim3(4, 4, BB * 4), 256>>>();
    k_patch_softmax<<<dim3(PP, BB), 256>>>();
    k_patch_h<<<dim3(4, 256, BB), 256>>>();
    k_glob_logits<<<dim3(49, 49, BB), 256>>>();
    k_glob_softmax<<<dim3(AA, BB), 256>>>();
    k_glob_h<<<dim3(49, 4, BB), 256>>>();
    k_upsample<<<(BB * CHW) / 256, 256>>>();
    k_proj<<<dim3(196, 4, BB), 256>>>(x, wproj, out);
}

// round 5
// speedup vs baseline: 1.7873x; 1.7873x over previous
#include <cuda_runtime.h>

// Problem constants
#define BB   8
#define CC   256
#define HH   112
#define WWD  112
#define HWSZ 12544          // 112*112
#define CHW  3211264        // 256*12544
#define PP   196            // patch area
#define AA   3136           // 56*56
#define TGD  56

#define PADA 20             // A[m][k] smem pad  (conflict-free frag reads)
#define PADB 136            // [k][n] smem pad   (conflict-free frag reads)

// ---------------- scratch (static device memory; no allocations) -------------
__device__ __align__(256) float d_q[(size_t)BB * CHW];
__device__ __align__(256) float d_k[(size_t)BB * CHW];
__device__ __align__(256) float d_v[(size_t)BB * CHW];
__device__ __align__(256) float d_h[(size_t)BB * CHW];
__device__ __align__(256) float d_qp[(size_t)BB * CC * AA];
__device__ __align__(256) float d_kp[(size_t)BB * CC * AA];
__device__ __align__(256) float d_vp[(size_t)BB * CC * AA];
__device__ __align__(256) float d_hg[(size_t)BB * CC * AA];
__device__ __align__(256) float d_attg[(size_t)BB * AA * AA];      // 314.7 MB
__device__ __align__(256) float d_attp[(size_t)BB * PP * PP];
__device__ __align__(256) float d_attp_part[(size_t)4 * BB * PP * PP];
__device__ float d_gnpart[BB * 128 * 2];
__device__ float d_sc[BB * CC];
__device__ float d_sh[BB * CC];
__device__ float d_effb[3 * BB * CC];

#define FMA4x4(acc, a, bb4) { \
    acc[0]  += a.x * bb4.x; acc[1]  += a.x * bb4.y; acc[2]  += a.x * bb4.z; acc[3]  += a.x * bb4.w; \
    acc[4]  += a.y * bb4.x; acc[5]  += a.y * bb4.y; acc[6]  += a.y * bb4.z; acc[7]  += a.y * bb4.w; \
    acc[8]  += a.z * bb4.x; acc[9]  += a.z * bb4.y; acc[10] += a.z * bb4.z; acc[11] += a.z * bb4.w; \
    acc[12] += a.w * bb4.x; acc[13] += a.w * bb4.y; acc[14] += a.w * bb4.z; acc[15] += a.w * bb4.w; }

// ---------------- tf32 mma helpers ------------------------------------------
__device__ __forceinline__ unsigned f2tf(float f) {
    unsigned u; asm("cvt.rna.tf32.f32 %0, %1;" : "=r"(u) : "f"(f)); return u;
}
__device__ __forceinline__ void mma8(float* c, const unsigned* a, unsigned b0, unsigned b1) {
    asm volatile(
        "mma.sync.aligned.m16n8k8.row.col.f32.tf32.tf32.f32 "
        "{%0,%1,%2,%3}, {%4,%5,%6,%7}, {%8,%9}, {%0,%1,%2,%3};"
        : "+f"(c[0]), "+f"(c[1]), "+f"(c[2]), "+f"(c[3])
        : "r"(a[0]), "r"(a[1]), "r"(a[2]), "r"(a[3]), "r"(b0), "r"(b1));
}

// ---------------- GroupNorm stats (two-pass, deterministic) ------------------
__global__ void k_gn_partial(const float* __restrict__ x) {
    int b = blockIdx.x, blk = blockIdx.y, t = threadIdx.x;
    const int chunk = CHW / 128;   // 25088
    const float* xb = x + (size_t)b * CHW + (size_t)blk * chunk;
    float s = 0.f, s2 = 0.f;
    for (int i = t; i < chunk; i += 256) { float v = xb[i]; s += v; s2 += v * v; }
    __shared__ float ss[256], sq[256];
    ss[t] = s; sq[t] = s2; __syncthreads();
    for (int o = 128; o > 0; o >>= 1) {
        if (t < o) { ss[t] += ss[t + o]; sq[t] += sq[t + o]; }
        __syncthreads();
    }
    if (t == 0) {
        d_gnpart[(b * 128 + blk) * 2]     = ss[0];
        d_gnpart[(b * 128 + blk) * 2 + 1] = sq[0];
    }
}

__global__ void k_gn_finalize(const float* __restrict__ gn_w, const float* __restrict__ gn_b) {
    int b = blockIdx.x, t = threadIdx.x;   // 128 threads
    __shared__ float ss[128], sq[128];
    ss[t] = d_gnpart[(b * 128 + t) * 2];
    sq[t] = d_gnpart[(b * 128 + t) * 2 + 1];
    __syncthreads();
    for (int o = 64; o > 0; o >>= 1) {
        if (t < o) { ss[t] += ss[t + o]; sq[t] += sq[t + o]; }
        __syncthreads();
    }
    __shared__ float mu_s, inv_s;
    if (t == 0) {
        float mu = ss[0] / (float)CHW;
        float var = sq[0] / (float)CHW - mu * mu;
        mu_s = mu; inv_s = rsqrtf(var + 1e-5f);
    }
    __syncthreads();
    float mu = mu_s, inv = inv_s;
    for (int c = t; c < CC; c += 128) {
        float sc = inv * gn_w[c];
        d_sc[b * CC + c] = sc;
        d_sh[b * CC + c] = gn_b[c] - mu * sc;
    }
}

// effective bias: eb[m][b][co] = bias[co] + sum_ci W[co,ci] * shift[b,ci]
__global__ void k_effbias(const float* __restrict__ wq, const float* __restrict__ wk,
                          const float* __restrict__ wv, const float* __restrict__ bq,
                          const float* __restrict__ bk, const float* __restrict__ bv) {
    int b = blockIdx.x, m = blockIdx.y, co = threadIdx.x;  // 256 threads
    const float* w  = (m == 0) ? wq : ((m == 1) ? wk : wv);
    const float* bs = (m == 0) ? bq : ((m == 1) ? bk : bv);
    float acc = bs[co];
    const float* sh = d_sh + b * CC;
    for (int ci = 0; ci < CC; ci++) acc += w[co * CC + ci] * sh[ci];
    d_effb[(m * BB + b) * CC + co] = acc;
}

// ---------------- tf32 tensor-core QKV GEMM ----------------------------------
// Single GEMM M=768 (stacked Wq/Wk/Wv), N=12544, K=256.
// B tile = x * groupnorm scale (shift folded into effbias).
__global__ void __launch_bounds__(256) k_qkv_tc(const float* __restrict__ x,
        const float* __restrict__ wq, const float* __restrict__ wk,
        const float* __restrict__ wv) {
    int b = blockIdx.z;
    int m0 = blockIdx.y * 128;          // 0..640
    int hw0 = blockIdx.x * 128;
    int t = threadIdx.x, lane = t & 31, wid = t >> 5;
    int gid = lane >> 2, t4 = lane & 3;
    int wm0 = (wid >> 2) * 64, wn0 = (wid & 3) * 32;
    int which = m0 >> 8, co0 = m0 & 255;
    const float* wsrc = (which == 0) ? wq : ((which == 1) ? wk : wv);
    __shared__ unsigned As[128 * PADA];
    __shared__ unsigned Bs[16 * PADB];
    __shared__ float scs[256];
    scs[t] = d_sc[b * CC + t];
    float acc[4][4][4];
#pragma unroll
    for (int i = 0; i < 4; i++)
#pragma unroll
        for (int j = 0; j < 4; j++)
#pragma unroll
            for (int r = 0; r < 4; r++) acc[i][j][r] = 0.f;
    const float* xb = x + (size_t)b * CHW + hw0;
    __syncthreads();
    for (int k0 = 0; k0 < 256; k0 += 16) {
#pragma unroll
        for (int r = 0; r < 2; r++) {
            int idx = t + r * 256;
            int row = idx >> 2, k4 = (idx & 3) * 4;
            float4 w4 = *(const float4*)&wsrc[(size_t)(co0 + row) * 256 + k0 + k4];
            As[row * PADA + k4]     = f2tf(w4.x);
            As[row * PADA + k4 + 1] = f2tf(w4.y);
            As[row * PADA + k4 + 2] = f2tf(w4.z);
            As[row * PADA + k4 + 3] = f2tf(w4.w);
        }
#pragma unroll
        for (int r = 0; r < 2; r++) {
            int idx = t + r * 256;
            int kk = idx >> 5, n4 = (idx & 31) * 4;
            float s = scs[k0 + kk];
            float4 x4 = *(const float4*)&xb[(size_t)(k0 + kk) * HWSZ + n4];
            Bs[kk * PADB + n4]     = f2tf(x4.x * s);
            Bs[kk * PADB + n4 + 1] = f2tf(x4.y * s);
            Bs[kk * PADB + n4 + 2] = f2tf(x4.z * s);
            Bs[kk * PADB + n4 + 3] = f2tf(x4.w * s);
        }
        __syncthreads();
#pragma unroll
        for (int ks = 0; ks < 16; ks += 8) {
            unsigned a[4][4], bf[4][2];
#pragma unroll
            for (int mt = 0; mt < 4; mt++) {
                int r0 = wm0 + mt * 16 + gid;
                a[mt][0] = As[r0 * PADA + ks + t4];
                a[mt][1] = As[(r0 + 8) * PADA + ks + t4];
                a[mt][2] = As[r0 * PADA + ks + t4 + 4];
                a[mt][3] = As[(r0 + 8) * PADA + ks + t4 + 4];
            }
#pragma unroll
            for (int nt = 0; nt < 4; nt++) {
                bf[nt][0] = Bs[(ks + t4) * PADB + wn0 + nt * 8 + gid];
                bf[nt][1] = Bs[(ks + t4 + 4) * PADB + wn0 + nt * 8 + gid];
            }
#pragma unroll
            for (int mt = 0; mt < 4; mt++)
#pragma unroll
                for (int nt = 0; nt < 4; nt++)
                    mma8(acc[mt][nt], a[mt], bf[nt][0], bf[nt][1]);
        }
        __syncthreads();
    }
    float* dst = (which == 0) ? d_q : ((which == 1) ? d_k : d_v);
    const float* eb = d_effb + (which * BB + b) * CC;
#pragma unroll
    for (int mt = 0; mt < 4; mt++) {
        int r0 = co0 + wm0 + mt * 16 + gid;
        float e0 = eb[r0], e1 = eb[r0 + 8];
#pragma unroll
        for (int nt = 0; nt < 4; nt++) {
            int col = hw0 + wn0 + nt * 8 + 2 * t4;
            *(float2*)&dst[(size_t)b * CHW + (size_t)r0 * HWSZ + col] =
                make_float2(acc[mt][nt][0] + e0, acc[mt][nt][1] + e0);
            *(float2*)&dst[(size_t)b * CHW + (size_t)(r0 + 8) * HWSZ + col] =
                make_float2(acc[mt][nt][2] + e1, acc[mt][nt][3] + e1);
        }
    }
}

// ---------------- 2x2 average pool of q,k,v ---------------------------------
__global__ void k_pool() {
    int i = blockIdx.x * 256 + threadIdx.x;      // < BB*CC*AA
    int xq = i % TGD; int r = i / TGD;
    int yq = r % TGD; r /= TGD;
    int c = r % CC;  int b = r / CC;
    size_t src = (size_t)b * CHW + (size_t)c * HWSZ + (size_t)(yq * 2) * WWD + xq * 2;
    float2 a0, a1;
    a0 = *(const float2*)&d_q[src]; a1 = *(const float2*)&d_q[src + WWD];
    d_qp[i] = 0.25f * (a0.x + a0.y + a1.x + a1.y);
    a0 = *(const float2*)&d_k[src]; a1 = *(const float2*)&d_k[src + WWD];
    d_kp[i] = 0.25f * (a0.x + a0.y + a1.x + a1.y);
    a0 = *(const float2*)&d_v[src]; a1 = *(const float2*)&d_v[src + WWD];
    d_vp[i] = 0.25f * (a0.x + a0.y + a1.x + a1.y);
}

// ---------------- patch logits (fp32, split-K) -------------------------------
__global__ void __launch_bounds__(256) k_patch_logits() {
    int bz = blockIdx.z; int b = bz >> 2, ks = bz & 3;
    int p0 = blockIdx.y * 64, q0 = blockIdx.x * 64;
    int t = threadIdx.x, tx = t & 15, ty = t >> 4;
    __shared__ float As[16][68], Bs[16][68];
    float acc[16];
#pragma unroll
    for (int i = 0; i < 16; i++) acc[i] = 0.f;
    const float* qb = d_q + (size_t)b * CHW;
    const float* kb = d_k + (size_t)b * CHW;
    int kk = t >> 4, m4 = (t & 15) * 4;
    int kend = (ks + 1) * 4096;
    for (int k0 = ks * 4096; k0 < kend; k0 += 16) {
        float4 va = make_float4(0.f, 0.f, 0.f, 0.f);
        if (p0 + m4 < PP) va = *(const float4*)&qb[(size_t)(k0 + kk) * PP + p0 + m4];
        *(float4*)&As[kk][m4] = va;
        float4 vb = make_float4(0.f, 0.f, 0.f, 0.f);
        if (q0 + m4 < PP) vb = *(const float4*)&kb[(size_t)(k0 + kk) * PP + q0 + m4];
        *(float4*)&Bs[kk][m4] = vb;
        __syncthreads();
#pragma unroll
        for (int u = 0; u < 16; u++) {
            float4 a4 = *(const float4*)&As[u][ty * 4];
            float4 b4 = *(const float4*)&Bs[u][tx * 4];
            FMA4x4(acc, a4, b4);
        }
        __syncthreads();
    }
#pragma unroll
    for (int i = 0; i < 4; i++) {
        int p = p0 + ty * 4 + i;
        if (p >= PP) continue;
#pragma unroll
        for (int j = 0; j < 4; j++) {
            int q = q0 + tx * 4 + j;
            if (q >= PP) continue;
            d_attp_part[(size_t)((ks * BB + b) * PP + p) * PP + q] = acc[i * 4 + j];
        }
    }
}

__global__ void k_patch_softmax() {
    int p = blockIdx.x, b = blockIdx.y, t = threadIdx.x;  // 256 threads
    float val = 0.f, v = -1e30f;
    if (t < PP) {
#pragma unroll
        for (int ks = 0; ks < 4; ks++)
            val += d_attp_part[(size_t)((ks * BB + b) * PP + p) * PP + t];
        val *= 0.0078125f;   // (C*S)^-0.5 = 1/128
        v = val;
    }
    __shared__ float red[256];
    red[t] = v; __syncthreads();
    for (int o = 128; o > 0; o >>= 1) {
        if (t < o) red[t] = fmaxf(red[t], red[t + o]);
        __syncthreads();
    }
    float mx = red[0];
    __syncthreads();
    float e = (t < PP) ? __expf(val - mx) : 0.f;
    red[t] = e; __syncthreads();
    for (int o = 128; o > 0; o >>= 1) {
        if (t < o) red[t] += red[t + o];
        __syncthreads();
    }
    float inv = 1.f / red[0];
    if (t < PP) d_attp[(size_t)(b * PP + p) * PP + t] = e * inv;
}

__global__ void __launch_bounds__(256) k_patch_h() {
    int b = blockIdx.z, m0 = blockIdx.y * 64, q0 = blockIdx.x * 64;
    int t = threadIdx.x, tx = t & 15, ty = t >> 4;
    __shared__ float As[16][68], Bs[16][68];
    float acc[16];
#pragma unroll
    for (int i = 0; i < 16; i++) acc[i] = 0.f;
    const float* vb = d_v + (size_t)b * CHW;
    const float* ab = d_attp + (size_t)b * PP * PP;
    int m = t >> 2, kb4 = (t & 3) * 4;
    for (int k0 = 0; k0 < PP; k0 += 16) {
        float4 va = make_float4(0.f, 0.f, 0.f, 0.f);
        if (k0 + kb4 < PP) va = *(const float4*)&vb[(size_t)(m0 + m) * PP + k0 + kb4];
        As[kb4][m] = va.x; As[kb4 + 1][m] = va.y; As[kb4 + 2][m] = va.z; As[kb4 + 3][m] = va.w;
        float4 vv = make_float4(0.f, 0.f, 0.f, 0.f);
        if (q0 + m < PP && k0 + kb4 < PP) vv = *(const float4*)&ab[(size_t)(q0 + m) * PP + k0 + kb4];
        Bs[kb4][m] = vv.x; Bs[kb4 + 1][m] = vv.y; Bs[kb4 + 2][m] = vv.z; Bs[kb4 + 3][m] = vv.w;
        __syncthreads();
#pragma unroll
        for (int u = 0; u < 16; u++) {
            float4 a4 = *(const float4*)&As[u][ty * 4];
            float4 b4 = *(const float4*)&Bs[u][tx * 4];
            FMA4x4(acc, a4, b4);
        }
        __syncthreads();
    }
#pragma unroll
    for (int i = 0; i < 4; i++) {
        int mm = m0 + ty * 4 + i;
#pragma unroll
        for (int j = 0; j < 4; j++) {
            int q = q0 + tx * 4 + j;
            if (q < PP) d_h[(size_t)b * CHW + (size_t)mm * PP + q] = 0.75f * acc[i * 4 + j];
        }
    }
}

// ---------------- global logits (tf32 mma): att[p,q] = sum_c qp[c,p] kp[c,q] -
__global__ void __launch_bounds__(256) k_glob_logits_tc() {
    int b = blockIdx.z, p0 = blockIdx.y * 128, q0 = blockIdx.x * 128;
    int t = threadIdx.x, lane = t & 31, wid = t >> 5;
    int gid = lane >> 2, t4 = lane & 3;
    int wm0 = (wid >> 2) * 64, wn0 = (wid & 3) * 32;
    __shared__ unsigned As[16 * PADB];     // [k][m]
    __shared__ unsigned Bs[16 * PADB];     // [k][n]
    float acc[4][4][4];
#pragma unroll
    for (int i = 0; i < 4; i++)
#pragma unroll
        for (int j = 0; j < 4; j++)
#pragma unroll
            for (int r = 0; r < 4; r++) acc[i][j][r] = 0.f;
    const float* qb = d_qp + (size_t)b * CC * AA;
    const float* kb = d_kp + (size_t)b * CC * AA;
    for (int k0 = 0; k0 < 256; k0 += 16) {
#pragma unroll
        for (int r = 0; r < 2; r++) {
            int idx = t + r * 256;
            int kk = idx >> 5, m4 = (idx & 31) * 4;
            float4 va = make_float4(0.f, 0.f, 0.f, 0.f);
            if (p0 + m4 < AA) va = *(const float4*)&qb[(size_t)(k0 + kk) * AA + p0 + m4];
            As[kk * PADB + m4]     = f2tf(va.x);
            As[kk * PADB + m4 + 1] = f2tf(va.y);
            As[kk * PADB + m4 + 2] = f2tf(va.z);
            As[kk * PADB + m4 + 3] = f2tf(va.w);
            float4 vb = make_float4(0.f, 0.f, 0.f, 0.f);
            if (q0 + m4 < AA) vb = *(const float4*)&kb[(size_t)(k0 + kk) * AA + q0 + m4];
            Bs[kk * PADB + m4]     = f2tf(vb.x);
            Bs[kk * PADB + m4 + 1] = f2tf(vb.y);
            Bs[kk * PADB + m4 + 2] = f2tf(vb.z);
            Bs[kk * PADB + m4 + 3] = f2tf(vb.w);
        }
        __syncthreads();
#pragma unroll
        for (int ks = 0; ks < 16; ks += 8) {
            unsigned a[4][4], bf[4][2];
#pragma unroll
            for (int mt = 0; mt < 4; mt++) {
                int m = wm0 + mt * 16 + gid;
                a[mt][0] = As[(ks + t4) * PADB + m];
                a[mt][1] = As[(ks + t4) * PADB + m + 8];
                a[mt][2] = As[(ks + t4 + 4) * PADB + m];
                a[mt][3] = As[(ks + t4 + 4) * PADB + m + 8];
            }
#pragma unroll
            for (int nt = 0; nt < 4; nt++) {
                bf[nt][0] = Bs[(ks + t4) * PADB + wn0 + nt * 8 + gid];
                bf[nt][1] = Bs[(ks + t4 + 4) * PADB + wn0 + nt * 8 + gid];
            }
#pragma unroll
            for (int mt = 0; mt < 4; mt++)
#pragma unroll
                for (int nt = 0; nt < 4; nt++)
                    mma8(acc[mt][nt], a[mt], bf[nt][0], bf[nt][1]);
        }
        __syncthreads();
    }
    size_t base = (size_t)b * AA * AA;
#pragma unroll
    for (int mt = 0; mt < 4; mt++) {
        int r0 = p0 + wm0 + mt * 16 + gid;
#pragma unroll
        for (int nt = 0; nt < 4; nt++) {
            int col = q0 + wn0 + nt * 8 + 2 * t4;
            if (col < AA) {
                if (r0 < AA)
                    *(float2*)&d_attg[base + (size_t)r0 * AA + col] =
                        make_float2(acc[mt][nt][0], acc[mt][nt][1]);
                if (r0 + 8 < AA)
                    *(float2*)&d_attg[base + (size_t)(r0 + 8) * AA + col] =
                        make_float2(acc[mt][nt][2], acc[mt][nt][3]);
            }
        }
    }
}

// row softmax over 3136 keys (applies C^-0.5 scale on read), row cached in smem
__global__ void k_glob_softmax() {
    int p = blockIdx.x, b = blockIdx.y, t = threadIdx.x;  // 256 threads
    float* row = d_attg + (size_t)(b * AA + p) * AA;
    __shared__ float sr[AA];
    __shared__ float red[256];
    float mx = -1e30f;
    for (int i = t; i < AA; i += 256) {
        float v = row[i] * 0.0625f;   // C^-0.5
        sr[i] = v; mx = fmaxf(mx, v);
    }
    red[t] = mx; __syncthreads();
    for (int o = 128; o > 0; o >>= 1) {
        if (t < o) red[t] = fmaxf(red[t], red[t + o]);
        __syncthreads();
    }
    mx = red[0];
    __syncthreads();
    float s = 0.f;
    for (int i = t; i < AA; i += 256) { float e = __expf(sr[i] - mx); sr[i] = e; s += e; }
    red[t] = s; __syncthreads();
    for (int o = 128; o > 0; o >>= 1) {
        if (t < o) red[t] += red[t + o];
        __syncthreads();
    }
    float inv = 1.f / red[0];
    for (int i = t; i < AA; i += 256) row[i] = sr[i] * inv;
}

// ---------------- global h (tf32 mma): hg[c,q] = sum_p vp[c,p] att[q,p] ------
__global__ void __launch_bounds__(256) k_glob_h_tc() {
    int b = blockIdx.z, c0 = blockIdx.y * 128, q0 = blockIdx.x * 128;
    int t = threadIdx.x, lane = t & 31, wid = t >> 5;
    int gid = lane >> 2, t4 = lane & 3;
    int wm0 = (wid >> 2) * 64, wn0 = (wid & 3) * 32;
    __shared__ unsigned As[128 * PADA];    // [m][k]
    __shared__ unsigned Bs[16 * PADB];     // [k][n] (transposed from att)
    float acc[4][4][4];
#pragma unroll
    for (int i = 0; i < 4; i++)
#pragma unroll
        for (int j = 0; j < 4; j++)
#pragma unroll
            for (int r = 0; r < 4; r++) acc[i][j][r] = 0.f;
    const float* vb = d_vp + (size_t)b * CC * AA;
    const float* ab = d_attg + (size_t)b * AA * AA;
    for (int k0 = 0; k0 < AA; k0 += 16) {
#pragma unroll
        for (int r = 0; r < 2; r++) {
            int idx = t + r * 256;
            int row = idx >> 2, k4 = (idx & 3) * 4;
            float4 va = *(const float4*)&vb[(size_t)(c0 + row) * AA + k0 + k4];
            As[row * PADA + k4]     = f2tf(va.x);
            As[row * PADA + k4 + 1] = f2tf(va.y);
            As[row * PADA + k4 + 2] = f2tf(va.z);
            As[row * PADA + k4 + 3] = f2tf(va.w);
            float4 vt = make_float4(0.f, 0.f, 0.f, 0.f);
            if (q0 + row < AA) vt = *(const float4*)&ab[(size_t)(q0 + row) * AA + k0 + k4];
            Bs[(k4)     * PADB + row] = f2tf(vt.x);
            Bs[(k4 + 1) * PADB + row] = f2tf(vt.y);
            Bs[(k4 + 2) * PADB + row] = f2tf(vt.z);
            Bs[(k4 + 3) * PADB + row] = f2tf(vt.w);
        }
        __syncthreads();
#pragma unroll
        for (int ks = 0; ks < 16; ks += 8) {
            unsigned a[4][4], bf[4][2];
#pragma unroll
            for (int mt = 0; mt < 4; mt++) {
                int r0 = wm0 + mt * 16 + gid;
                a[mt][0] = As[r0 * PADA + ks + t4];
                a[mt][1] = As[(r0 + 8) * PADA + ks + t4];
                a[mt][2] = As[r0 * PADA + ks + t4 + 4];
                a[mt][3] = As[(r0 + 8) * PADA + ks + t4 + 4];
            }
#pragma unroll
            for (int nt = 0; nt < 4; nt++) {
                bf[nt][0] = Bs[(ks + t4) * PADB + wn0 + nt * 8 + gid];
                bf[nt][1] = Bs[(ks + t4 + 4) * PADB + wn0 + nt * 8 + gid];
            }
#pragma unroll
            for (int mt = 0; mt < 4; mt++)
#pragma unroll
                for (int nt = 0; nt < 4; nt++)
                    mma8(acc[mt][nt], a[mt], bf[nt][0], bf[nt][1]);
        }
        __syncthreads();
    }
#pragma unroll
    for (int mt = 0; mt < 4; mt++) {
        int r0 = c0 + wm0 + mt * 16 + gid;
#pragma unroll
        for (int nt = 0; nt < 4; nt++) {
            int col = q0 + wn0 + nt * 8 + 2 * t4;
            if (col < AA) {
                *(float2*)&d_hg[(size_t)b * CC * AA + (size_t)r0 * AA + col] =
                    make_float2(acc[mt][nt][0], acc[mt][nt][1]);
                *(float2*)&d_hg[(size_t)b * CC * AA + (size_t)(r0 + 8) * AA + col] =
                    make_float2(acc[mt][nt][2], acc[mt][nt][3]);
            }
        }
    }
}

// ---------------- bilinear 56->112 upsample (half-pixel) + combine -----------
__global__ void k_upsample() {
    int i = blockIdx.x * 256 + threadIdx.x;   // < BB*CHW
    int xo = i % WWD; int r = i / WWD;
    int yo = r % HH;  r /= HH;
    int c = r % CC;   int b = r / CC;
    float sx = xo * 0.5f - 0.25f, sy = yo * 0.5f - 0.25f;
    float fx = floorf(sx), fy = floorf(sy);
    float wx = sx - fx, wy = sy - fy;
    int x0 = max((int)fx, 0), x1 = min((int)fx + 1, TGD - 1);
    int y0 = max((int)fy, 0), y1 = min((int)fy + 1, TGD - 1);
    const float* hb = d_hg + (size_t)(b * CC + c) * AA;
    float v00 = hb[y0 * TGD + x0], v01 = hb[y0 * TGD + x1];
    float v10 = hb[y1 * TGD + x0], v11 = hb[y1 * TGD + x1];
    float v = (1.f - wy) * ((1.f - wx) * v00 + wx * v01)
            +        wy  * ((1.f - wx) * v10 + wx * v11);
    d_h[i] += 0.25f * v;   // d_h already holds 0.75*h_patch
}

// ---------------- proj GEMM (tf32 mma) + residual ----------------------------
__global__ void __launch_bounds__(256) k_proj_tc(const float* __restrict__ x,
        const float* __restrict__ wp, float* __restrict__ out) {
    int b = blockIdx.z;
    int co0 = blockIdx.y * 128;
    int hw0 = blockIdx.x * 128;
    int t = threadIdx.x, lane = t & 31, wid = t >> 5;
    int gid = lane >> 2, t4 = lane & 3;
    int wm0 = (wid >> 2) * 64, wn0 = (wid & 3) * 32;
    __shared__ unsigned As[128 * PADA];
    __shared__ unsigned Bs[16 * PADB];
    float acc[4][4][4];
#pragma unroll
    for (int i = 0; i < 4; i++)
#pragma unroll
        for (int j = 0; j < 4; j++)
#pragma unroll
            for (int r = 0; r < 4; r++) acc[i][j][r] = 0.f;
    const float* hb = d_h + (size_t)b * CHW + hw0;
    for (int k0 = 0; k0 < 256; k0 += 16) {
#pragma unroll
        for (int r = 0; r < 2; r++) {
            int idx = t + r * 256;
            int row = idx >> 2, k4 = (idx & 3) * 4;
            float4 w4 = *(const float4*)&wp[(size_t)(co0 + row) * 256 + k0 + k4];
            As[row * PADA + k4]     = f2tf(w4.x);
            As[row * PADA + k4 + 1] = f2tf(w4.y);
            As[row * PADA + k4 + 2] = f2tf(w4.z);
            As[row * PADA + k4 + 3] = f2tf(w4.w);
        }
#pragma unroll
        for (int r = 0; r < 2; r++) {
            int idx = t + r * 256;
            int kk = idx >> 5, n4 = (idx & 31) * 4;
            float4 h4 = *(const float4*)&hb[(size_t)(k0 + kk) * HWSZ + n4];
            Bs[kk * PADB + n4]     = f2tf(h4.x);
            Bs[kk * PADB + n4 + 1] = f2tf(h4.y);
            Bs[kk * PADB + n4 + 2] = f2tf(h4.z);
            Bs[kk * PADB + n4 + 3] = f2tf(h4.w);
        }
        __syncthreads();
#pragma unroll
        for (int ks = 0; ks < 16; ks += 8) {
            unsigned a[4][4], bf[4][2];
#pragma unroll
            for (int mt = 0; mt < 4; mt++) {
                int r0 = wm0 + mt * 16 + gid;
                a[mt][0] = As[r0 * PADA + ks + t4];
                a[mt][1] = As[(r0 + 8) * PADA + ks + t4];
                a[mt][2] = As[r0 * PADA + ks + t4 + 4];
                a[mt][3] = As[(r0 + 8) * PADA + ks + t4 + 4];
            }
#pragma unroll
            for (int nt = 0; nt < 4; nt++) {
                bf[nt][0] = Bs[(ks + t4) * PADB + wn0 + nt * 8 + gid];
                bf[nt][1] = Bs[(ks + t4 + 4) * PADB + wn0 + nt * 8 + gid];
            }
#pragma unroll
            for (int mt = 0; mt < 4; mt++)
#pragma unroll
                for (int nt = 0; nt < 4; nt++)
                    mma8(acc[mt][nt], a[mt], bf[nt][0], bf[nt][1]);
        }
        __syncthreads();
    }
#pragma unroll
    for (int mt = 0; mt < 4; mt++) {
        int r0 = co0 + wm0 + mt * 16 + gid;
#pragma unroll
        for (int nt = 0; nt < 4; nt++) {
            int col = hw0 + wn0 + nt * 8 + 2 * t4;
            size_t o0 = (size_t)b * CHW + (size_t)r0 * HWSZ + col;
            size_t o1 = (size_t)b * CHW + (size_t)(r0 + 8) * HWSZ + col;
            float2 x0 = *(const float2*)&x[o0];
            float2 x1 = *(const float2*)&x[o1];
            *(float2*)&out[o0] = make_float2(x0.x + acc[mt][nt][0], x0.y + acc[mt][nt][1]);
            *(float2*)&out[o1] = make_float2(x1.x + acc[mt][nt][2], x1.y + acc[mt][nt][3]);
        }
    }
}

// ---------------- launcher ---------------------------------------------------
extern "C" void kernel_launch(void* const* d_in, const int* in_sizes, int n_in,
                              void* d_out, int out_size) {
    const float* x     = (const float*)d_in[0];
    const float* gn_w  = (const float*)d_in[1];
    const float* gn_b  = (const float*)d_in[2];
    const float* wq    = (const float*)d_in[3];
    const float* bq    = (const float*)d_in[4];
    const float* wk    = (const float*)d_in[5];
    const float* bk    = (const float*)d_in[6];
    const float* wv    = (const float*)d_in[7];
    const float* bv    = (const float*)d_in[8];
    const float* wproj = (const float*)d_in[9];
    float* out = (float*)d_out;

    k_gn_partial<<<dim3(BB, 128), 256>>>(x);
    k_gn_finalize<<<BB, 128>>>(gn_w, gn_b);
    k_effbias<<<dim3(BB, 3), 256>>>(wq, wk, wv, bq, bk, bv);
    k_qkv_tc<<<dim3(98, 6, BB), 256>>>(x, wq, wk, wv);
    k_pool<<<(BB * CC * AA) / 256, 256>>>();
    k_patch_logits<<<dim3(4, 4, BB * 4), 256>>>();
    k_patch_softmax<<<dim3(PP, BB), 256>>>();
    k_patch_h<<<dim3(4, 256, BB), 256>>>();
    k_glob_logits_tc<<<dim3(25, 25, BB), 256>>>();
    k_glob_softmax<<<dim3(AA, BB), 256>>>();
    k_glob_h_tc<<<dim3(25, 2, BB), 256>>>();
    k_upsample<<<(BB * CHW) / 256, 256>>>();
    k_proj_tc<<<dim3(98, 2, BB), 256>>>(x, wproj, out);
}